// round 16
// baseline (speedup 1.0000x reference)
#include <cuda_runtime.h>
#include <cuda_bf16.h>
#include <mma.h>
#include <cstdint>
#include <cstddef>

using namespace nvcuda;

// ---------------- device scratch (static, no runtime alloc) ----------------
__device__ float g_preF[(size_t)1024 * 64 * 2048];      // x@Wf[:512]+bf, time-major [t][b][g]
__device__ float g_preB[(size_t)1024 * 64 * 2048];      // x@Wb[:512]+bb
__device__ float g_base[2][256][2048];                  // embed@W[:512] per vocab entry
__device__ uint2 g_dropPack[(size_t)65536 * 128];       // per row: (d, bits(e[tok][d])) dropped entries
__device__ unsigned int g_dropN[65536];                 // per row: dropped count
__device__ uint2 g_kz[2 * 1024];                        // per-step zoneout keys (fwd, bwd)
__device__ uint2 g_kd;                                  // dropout key
// h exchange, TRANSPOSED: block = [128 k-rows][136 m] bf16 (m: 0-63 = h_hi(b), 64-127 = h_lo(b)).
// Producer CTA owns 8 contiguous k-rows -> fully coalesced stores.
#define LDAB 136
#define A_BLOCK_BYTES 34816u                            // 128*136*2
#define A_BLK_ELEMS (128 * LDAB)
__device__ __align__(1024) unsigned char g_hA[2][2][4][34816];
// per-CTA step flags, padded to 128B
struct FlagLine { unsigned v; unsigned pad[31]; };
__device__ FlagLine g_flag[2][64];
// time-major output scratch: [t][dir][d][b]
__device__ float g_outS[(size_t)1024 * 2 * 512 * 64];

// ---------------- JAX threefry2x32 (bit-exact, 20 rounds) ----------------
__device__ __forceinline__ uint32_t rotl32(uint32_t x, int r) { return (x << r) | (x >> (32 - r)); }

__device__ __forceinline__ void tf2x32(uint32_t k0, uint32_t k1, uint32_t& x0, uint32_t& x1) {
    uint32_t k2 = k0 ^ k1 ^ 0x1BD11BDAu;
    x0 += k0; x1 += k1;
#define TFR(r) { x0 += x1; x1 = rotl32(x1, r); x1 ^= x0; }
    TFR(13) TFR(15) TFR(26) TFR(6)   x0 += k1; x1 += k2 + 1u;
    TFR(17) TFR(29) TFR(16) TFR(24)  x0 += k2; x1 += k0 + 2u;
    TFR(13) TFR(15) TFR(26) TFR(6)   x0 += k0; x1 += k1 + 3u;
    TFR(17) TFR(29) TFR(16) TFR(24)  x0 += k1; x1 += k2 + 4u;
    TFR(13) TFR(15) TFR(26) TFR(6)   x0 += k2; x1 += k0 + 5u;
#undef TFR
}

__device__ __forceinline__ uint32_t pbits(uint32_t k0, uint32_t k1, uint32_t i) {
    uint32_t x0 = 0u, x1 = i;
    tf2x32(k0, k1, x0, x1);
    return x0 ^ x1;
}

__device__ __forceinline__ float u01(uint32_t bits) {
    return __uint_as_float((bits >> 9) | 0x3f800000u) - 1.0f;
}

// ---------------- MUFU-free transcendentals ----------------
__device__ __forceinline__ float sigm_fast(float x) {
    float t = -x * 1.44269504088896341f;
    t = fminf(fmaxf(t, -126.0f), 126.0f);
    float z = t + 12582912.0f;
    int ii = __float_as_int(z) - 0x4B400000;
    float f = t - (z - 12582912.0f);
    float p =            1.54035303933816e-4f;
    p = fmaf(p, f, 1.33335581464284e-3f);
    p = fmaf(p, f, 9.61812910762848e-3f);
    p = fmaf(p, f, 5.55041086648216e-2f);
    p = fmaf(p, f, 2.40226506959101e-1f);
    p = fmaf(p, f, 6.93147180559945e-1f);
    p = fmaf(p, f, 1.0f);
    float e = p * __int_as_float((ii + 127) << 23);
    float d = 1.0f + e;
    float y = __int_as_float(0x7EF311C3 - __float_as_int(d));
    y = y * (2.0f - d * y);
    y = y * (2.0f - d * y);
    y = y * (2.0f - d * y);
    return y;
}
__device__ __forceinline__ float tanh_fast(float x) {
    return fmaf(2.0f, sigm_fast(2.0f * x), -1.0f);
}

// ---------------- K1: setup — keys, flags, zero g_hA ----------------
__global__ void setup_kernel() {
    int tid = threadIdx.x;
    if (blockIdx.x == 0) {
        __shared__ uint32_t s[4];
        if (tid < 128) g_flag[tid >> 6][tid & 63].v = 0u;
        if (tid == 0) {
            uint32_t a, b;
            a = 0u; b = 0u; tf2x32(0u, 42u, a, b); g_kd = make_uint2(a, b);
            a = 0u; b = 1u; tf2x32(0u, 42u, a, b); s[0] = a; s[1] = b;   // kf
            a = 0u; b = 2u; tf2x32(0u, 42u, a, b); s[2] = a; s[3] = b;   // kb
        }
        __syncthreads();
        if (tid < 2) {
            uint32_t k0 = s[tid * 2], k1 = s[tid * 2 + 1];
            for (int t = 0; t < 1024; ++t) {
                uint32_t z0 = 0u, z1 = 0u; tf2x32(k0, k1, z0, z1);
                uint32_t n0 = 0u, n1 = 1u; tf2x32(k0, k1, n0, n1);
                g_kz[tid * 1024 + t] = make_uint2(z0, z1);
                k0 = n0; k1 = n1;
            }
        }
    }
    uint32_t* hA = (uint32_t*)&g_hA[0][0][0][0];
    for (unsigned i = blockIdx.x * 256u + tid; i < 139264u; i += gridDim.x * 256u)
        hA[i] = 0u;
}

// ---------------- K2: base table + dropout lists (fused) ----------------
__global__ void __launch_bounds__(256) basedrop_kernel(const int* __restrict__ tokens,
                                                       const float* __restrict__ embed,
                                                       const float* __restrict__ Wf,
                                                       const float* __restrict__ Wb) {
    int bid = blockIdx.x;
    int tid = threadIdx.x;
    if (bid < 1024) {
        int dir = bid >> 9;
        int rem = bid & 511;
        int gx = rem & 7, v0 = (rem >> 3) * 4;
        const float* W = dir ? Wb : Wf;
        int g = gx * 256 + tid;
        float acc0 = 0.f, acc1 = 0.f, acc2 = 0.f, acc3 = 0.f;
#pragma unroll 4
        for (int d = 0; d < 512; ++d) {
            float w = W[(size_t)d * 2048 + g];
            acc0 = fmaf(embed[(size_t)(v0 + 0) * 512 + d], w, acc0);
            acc1 = fmaf(embed[(size_t)(v0 + 1) * 512 + d], w, acc1);
            acc2 = fmaf(embed[(size_t)(v0 + 2) * 512 + d], w, acc2);
            acc3 = fmaf(embed[(size_t)(v0 + 3) * 512 + d], w, acc3);
        }
        g_base[dir][v0 + 0][g] = acc0;
        g_base[dir][v0 + 1][g] = acc1;
        g_base[dir][v0 + 2][g] = acc2;
        g_base[dir][v0 + 3][g] = acc3;
    } else {
        unsigned row = ((unsigned)(bid - 1024) * 256u + (unsigned)tid) >> 5;
        int lane = tid & 31;
        uint2 kd = g_kd;
        int tok = tokens[row];
        const float* erow = &embed[(size_t)tok * 512];
        uint2* outp = &g_dropPack[(size_t)row * 128];
        unsigned count = 0;
#pragma unroll 4
        for (int it = 0; it < 16; ++it) {
            int d = it * 32 + lane;
            uint32_t bits = pbits(kd.x, kd.y, row * 512u + (unsigned)d);
            bool dropped = !(u01(bits) < 0.9f);
            unsigned m = __ballot_sync(0xffffffffu, dropped);
            if (dropped) {
                unsigned pos = count + __popc(m & ((1u << lane) - 1u));
                outp[pos] = make_uint2((unsigned)d, __float_as_uint(erow[d]));
            }
            count += __popc(m);
        }
        if (lane == 0) g_dropN[row] = count;
    }
}

// ---------------- K3: projection (base + sparse dropout correction) ----------------
#define CORR_SMEM (512 * 64 * 4)

__global__ void __launch_bounds__(256, 1) proj_corr_kernel(const int* __restrict__ tokens,
                                                           const float* __restrict__ Wf,
                                                           const float* __restrict__ Wb,
                                                           const float* __restrict__ bf,
                                                           const float* __restrict__ bb) {
    extern __shared__ float sW[];
    int dir = blockIdx.x >> 5;
    int slice = blockIdx.x & 31;
    int g0 = slice * 64;
    const float* W = dir ? Wb : Wf;
    const float* bias = dir ? bb : bf;
    float* pre = dir ? g_preB : g_preF;
    const float* base = &g_base[dir][0][0];
    int tid = threadIdx.x;

    for (int i = tid; i < 512 * 64; i += 256)
        sW[i] = W[(size_t)(i >> 6) * 2048 + g0 + (i & 63)];
    __syncthreads();

    int lane = tid & 31, w = tid >> 5;
    float2 bv = *(const float2*)&bias[g0 + lane * 2];
    int rEnd = blockIdx.y * 4096 + 4096;
    for (int r = blockIdx.y * 4096 + w; r < rEnd; r += 8) {
        int tok = tokens[r];
        unsigned n = g_dropN[r];
        const uint2* lst = &g_dropPack[(size_t)r * 128];
        float2 acc = *(const float2*)&base[(size_t)tok * 2048 + g0 + lane * 2];
        for (unsigned j0 = 0; j0 < n; j0 += 32) {
            uint2 e = make_uint2(0u, 0u);
            if (j0 + lane < n) e = __ldcg(&lst[j0 + lane]);
#pragma unroll
            for (int jj = 0; jj < 32; ++jj) {
                unsigned dx = __shfl_sync(0xffffffffu, e.x, jj);
                unsigned dv = __shfl_sync(0xffffffffu, e.y, jj);
                float val = __uint_as_float(dv);
                float2 wv = *(const float2*)&sW[dx * 64 + lane * 2];
                acc.x = fmaf(-val, wv.x, acc.x);
                acc.y = fmaf(-val, wv.y, acc.y);
            }
        }
        int b = r >> 10, t = r & 1023;
        float2 o;
        o.x = fmaf(acc.x, (1.0f / 0.9f), bv.x);
        o.y = fmaf(acc.y, (1.0f / 0.9f), bv.y);
        *(float2*)&pre[(((size_t)t * 64) + b) * 2048 + g0 + lane * 2] = o;
    }
}

// ---------------- K4: persistent bidirectional LSTM scan ----------------
#define LDB 520
#define SA_OFF   0
#define SBHI_OFF 139264
#define SBLO_OFF (SBHI_OFF + 32 * LDB * 2)
#define SD_OFF   (SBLO_OFF + 32 * LDB * 2)
#define LDD 40
#define SCAN_SMEM (SD_OFF + 128 * LDD * 4)

__device__ __forceinline__ void wait_par(uint32_t bar, unsigned p) {
    asm volatile(
        "{\n\t.reg .pred P;\n\t"
        "WL_%=:\n\t"
        "mbarrier.try_wait.parity.acquire.cta.shared::cta.b64 P, [%0], %1, 0x989680;\n\t"
        "@P bra WD_%=;\n\t"
        "bra WL_%=;\n\t"
        "WD_%=:\n\t}"
        :: "r"(bar), "r"(p) : "memory");
}
__device__ __forceinline__ void tma_block(uint32_t dst, const unsigned char* src, uint32_t bar) {
    asm volatile("mbarrier.arrive.expect_tx.shared.b64 _, [%0], %1;"
                 :: "r"(bar), "r"(A_BLOCK_BYTES) : "memory");
    asm volatile("cp.async.bulk.shared::cta.global.mbarrier::complete_tx::bytes [%0], [%1], %2, [%3];"
                 :: "r"(dst), "l"(src), "r"(A_BLOCK_BYTES), "r"(bar) : "memory");
}
__device__ __forceinline__ void stg_u16(void* p, unsigned short v) {
    asm volatile("st.global.cg.u16 [%0], %1;" :: "l"(p), "h"(v) : "memory");
}

__global__ void __launch_bounds__(256, 1) scan_kernel(const int* __restrict__ lengths,
                                                      const float* __restrict__ Wf,
                                                      const float* __restrict__ Wb) {
    extern __shared__ unsigned char smem[];
    __nv_bfloat16* sA   = (__nv_bfloat16*)(smem + SA_OFF);     // [k][m] per block, ld=136
    __nv_bfloat16* sBhi = (__nv_bfloat16*)(smem + SBHI_OFF);
    __nv_bfloat16* sBlo = (__nv_bfloat16*)(smem + SBLO_OFF);
    float* sD  = (float*)(smem + SD_OFF);
    float* sD2 = (float*)(smem + SA_OFF);            // reuses block0 A region post-consumption
    __shared__ int sLen[64];
    __shared__ __align__(8) unsigned long long mbars[4];

    int dir = blockIdx.x >> 6, cta = blockIdx.x & 63, d0 = cta * 8;
    int tid = threadIdx.x, wid = tid >> 5, lane = tid & 31;
    const float* W = dir ? Wb : Wf;

    uint32_t sA_addr = (uint32_t)__cvta_generic_to_shared(sA);
    uint32_t bar[4];
#pragma unroll
    for (int j = 0; j < 4; ++j) bar[j] = (uint32_t)__cvta_generic_to_shared(&mbars[j]);
    if (tid < 4)
        asm volatile("mbarrier.init.shared.b64 [%0], 1;" :: "r"(bar[tid]) : "memory");

    for (int i = tid; i < 32 * 512; i += 256) {
        int n = i & 31, k = i >> 5;
        float w = W[(size_t)(512 + k) * 2048 + ((n >> 3) << 9) + d0 + (n & 7)];
        __nv_bfloat16 hi = __float2bfloat16(w);
        __nv_bfloat16 lo = __float2bfloat16(w - __bfloat162float(hi));
        sBhi[n * LDB + k] = hi;
        sBlo[n * LDB + k] = lo;
    }
    if (tid < 64) sLen[tid] = lengths[tid];
    __syncthreads();

    if (tid < 4) tma_block(sA_addr + (unsigned)tid * A_BLOCK_BYTES, g_hA[dir][0][tid], bar[tid]);

    int q = tid >> 6, b = tid & 63;
    int dd = q * 2, d = d0 + dd;
    float c0r = 0.f, c1r = 0.f;
    float hp0r = 0.f, hp1r = 0.f;
    const float* pre = dir ? g_preB : g_preF;
    int mg = wid & 3, nt = wid >> 2;
    bool isHiWarp = (mg < 2);
    int blk = cta >> 4;
    unsigned klocal = (unsigned)(d & 127);           // k-row within block (this thread's dim d)
    // transposed layout: element (k, m) at (k*136 + m)*2 bytes
    size_t oH0 = (size_t)(klocal * LDAB + b) * 2;
    size_t oH1 = (size_t)((klocal + 1) * LDAB + b) * 2;
    size_t oL0 = (size_t)(klocal * LDAB + b + 64) * 2;
    size_t oL1 = (size_t)((klocal + 1) * LDAB + b + 64) * 2;
    unsigned p0 = (unsigned)(b * 512 + d);

    for (int s = 0; s < 1024; ++s) {
        int tx = dir ? (1023 - s) : s;
        unsigned par = (unsigned)(s & 1);

        size_t prow = ((size_t)tx * 64 + b) * 2048 + (size_t)d;
        float2 pxi = *(const float2*)&pre[prow];
        float2 pxg = *(const float2*)&pre[prow + 512];
        float2 pxf = *(const float2*)&pre[prow + 1024];
        float2 pxo = *(const float2*)&pre[prow + 1536];
        uint2 kz = __ldg(&g_kz[dir * 1024 + s]);
        bool kh0 = u01(pbits(kz.x, kz.y, p0)) < 0.1f;
        bool kh1 = u01(pbits(kz.x, kz.y, p0 + 1u)) < 0.1f;
        bool kc0 = u01(pbits(kz.x, kz.y, p0 + 32768u)) < 0.1f;
        bool kc1 = u01(pbits(kz.x, kz.y, p0 + 32769u)) < 0.1f;

        wmma::fragment<wmma::accumulator, 16, 16, 16, float> acc0, acc1, acc2, acc3;
        wmma::fill_fragment(acc0, 0.0f);
        wmma::fill_fragment(acc1, 0.0f);
        if (isHiWarp) { wmma::fill_fragment(acc2, 0.0f); wmma::fill_fragment(acc3, 0.0f); }
        const __nv_bfloat16* bh_base = sBhi + nt * 16 * LDB;
        const __nv_bfloat16* bl_base = sBlo + nt * 16 * LDB;

#pragma unroll 1
        for (int bk = 0; bk < 4; ++bk) {
            wait_par(bar[bk], par);
            const __nv_bfloat16* ablk = sA + bk * A_BLK_ELEMS;
            const __nv_bfloat16* bhp = bh_base + bk * 128;
            const __nv_bfloat16* blp = bl_base + bk * 128;
#pragma unroll 4
            for (int kt = 0; kt < 8; ++kt) {
                wmma::fragment<wmma::matrix_a, 16, 16, 16, __nv_bfloat16, wmma::col_major> a0f, a1f;
                wmma::fragment<wmma::matrix_b, 16, 16, 16, __nv_bfloat16, wmma::col_major> bhf;
                wmma::load_matrix_sync(a0f, ablk + (kt * 16) * LDAB + mg * 32, LDAB);
                wmma::load_matrix_sync(a1f, ablk + (kt * 16) * LDAB + mg * 32 + 16, LDAB);
                wmma::load_matrix_sync(bhf, bhp + kt * 16, LDB);
                wmma::mma_sync(acc0, a0f, bhf, acc0);
                wmma::mma_sync(acc1, a1f, bhf, acc1);
                if (isHiWarp) {
                    wmma::fragment<wmma::matrix_b, 16, 16, 16, __nv_bfloat16, wmma::col_major> blf;
                    wmma::load_matrix_sync(blf, blp + kt * 16, LDB);
                    wmma::mma_sync(acc2, a0f, blf, acc2);
                    wmma::mma_sync(acc3, a1f, blf, acc3);
                }
            }
        }
        wmma::store_matrix_sync(sD + (mg * 2) * 16 * LDD + nt * 16, acc0, LDD, wmma::mem_row_major);
        wmma::store_matrix_sync(sD + (mg * 2 + 1) * 16 * LDD + nt * 16, acc1, LDD, wmma::mem_row_major);
        __syncthreads();
        if (isHiWarp) {
            wmma::store_matrix_sync(sD2 + (mg * 2) * 16 * LDD + nt * 16, acc2, LDD, wmma::mem_row_major);
            wmma::store_matrix_sync(sD2 + (mg * 2 + 1) * 16 * LDD + nt * 16, acc3, LDD, wmma::mem_row_major);
        }
        __syncthreads();

        if (dir && (1023 - s) < sLen[b] - 1) { c0r = 0.f; c1r = 0.f; }
        const float* dt = &sD[b * LDD];
        const float* db = &sD[(b + 64) * LDD];
        const float* d2 = &sD2[b * LDD];
        float a_i0 = dt[dd] + db[dd] + d2[dd];
        float a_i1 = dt[dd + 1] + db[dd + 1] + d2[dd + 1];
        float a_g0 = dt[8 + dd] + db[8 + dd] + d2[8 + dd];
        float a_g1 = dt[9 + dd] + db[9 + dd] + d2[9 + dd];
        float a_f0 = dt[16 + dd] + db[16 + dd] + d2[16 + dd];
        float a_f1 = dt[17 + dd] + db[17 + dd] + d2[17 + dd];
        float a_o0 = dt[24 + dd] + db[24 + dd] + d2[24 + dd];
        float a_o1 = dt[25 + dd] + db[25 + dd] + d2[25 + dd];
        float f0 = sigm_fast(pxf.x + a_f0 + 1.f), f1 = sigm_fast(pxf.y + a_f1 + 1.f);
        float o0 = sigm_fast(pxo.x + a_o0), o1 = sigm_fast(pxo.y + a_o1);
        float cn0 = f0 * c0r + sigm_fast(pxi.x + a_i0) * tanh_fast(pxg.x + a_g0);
        float cn1 = f1 * c1r + sigm_fast(pxi.y + a_i1) * tanh_fast(pxg.y + a_g1);
        float hn0 = o0 * tanh_fast(cn0);
        float hn1 = o1 * tanh_fast(cn1);
        float ho0 = kh0 ? hp0r : hn0;
        float ho1 = kh1 ? hp1r : hn1;
        c0r = kc0 ? c0r : cn0;
        c1r = kc1 ? c1r : cn1;

        float w0 = ho0, w1 = ho1;
        if (dir && (1022 - s) < sLen[b] - 1) { w0 = 0.f; w1 = 0.f; }
        hp0r = w0; hp1r = w1;
        __nv_bfloat16 h0 = __float2bfloat16(w0), h1 = __float2bfloat16(w1);
        __nv_bfloat16 l0 = __float2bfloat16(w0 - __bfloat162float(h0));
        __nv_bfloat16 l1 = __float2bfloat16(w1 - __bfloat162float(h1));
        unsigned char* hw = g_hA[dir][(s + 1) & 1][blk];
        // coalesced: lanes (consecutive b) write consecutive 2B within a k-row
        stg_u16(hw + oH0, __bfloat16_as_ushort(h0));
        stg_u16(hw + oH1, __bfloat16_as_ushort(h1));
        stg_u16(hw + oL0, __bfloat16_as_ushort(l0));
        stg_u16(hw + oL1, __bfloat16_as_ushort(l1));

        float* os = &g_outS[(((size_t)tx * 2 + dir) * 512 + d) * 64 + b];

        __syncthreads();
        if (s < 1023) {
            if (tid == 0) {
                __threadfence();
                *(volatile unsigned*)&g_flag[dir][cta].v = (unsigned)(s + 1);
            }
            os[0] = ho0;
            os[64] = ho1;
            if (wid < 4) {
                if (lane < 16) {
                    volatile unsigned* f = &g_flag[dir][wid * 16 + lane].v;
                    while (*f < (unsigned)(s + 1)) { }   // bare spin: 64 pollers/line, L2-latency throttled
                }
                __syncwarp();
                if (lane == 0)
                    tma_block(sA_addr + (unsigned)wid * A_BLOCK_BYTES,
                              g_hA[dir][(s + 1) & 1][wid], bar[wid]);
            }
        } else {
            os[0] = ho0;
            os[64] = ho1;
        }
    }
}

// ---------------- K5: transpose g_outS -> out [b][l][2*512] ----------------
__global__ void __launch_bounds__(256) transpose_kernel(float* __restrict__ out) {
    __shared__ float sT[32][65];
    unsigned bid = blockIdx.x;
    int dblk = bid & 15;
    int dir = (bid >> 4) & 1;
    int l = bid >> 5;
    const float* src = &g_outS[(((size_t)l * 2 + dir) * 512 + dblk * 32) * 64];
    int tid = threadIdx.x;
#pragma unroll
    for (int i = 0; i < 8; ++i) {
        int idx = tid + i * 256;
        int r = idx >> 6, c = idx & 63;
        sT[r][c] = src[idx];
    }
    __syncthreads();
#pragma unroll
    for (int i = 0; i < 8; ++i) {
        int idx = tid + i * 256;
        int b = idx >> 5, r = idx & 31;
        out[((size_t)b * 1024 + l) * 1024 + dir * 512 + dblk * 32 + r] = sT[r][b];
    }
}

// ---------------- launch ----------------
extern "C" void kernel_launch(void* const* d_in, const int* in_sizes, int n_in,
                              void* d_out, int out_size) {
    (void)in_sizes; (void)n_in; (void)out_size;
    const int*   tokens  = (const int*)d_in[0];
    const int*   lengths = (const int*)d_in[1];
    const float* embed   = (const float*)d_in[2];
    const float* Wf      = (const float*)d_in[3];
    const float* bf      = (const float*)d_in[4];
    const float* Wb      = (const float*)d_in[5];
    const float* bb      = (const float*)d_in[6];
    float* out = (float*)d_out;

    cudaFuncSetAttribute(scan_kernel, cudaFuncAttributeMaxDynamicSharedMemorySize, SCAN_SMEM);
    cudaFuncSetAttribute(proj_corr_kernel, cudaFuncAttributeMaxDynamicSharedMemorySize, CORR_SMEM);

    setup_kernel<<<64, 256>>>();
    basedrop_kernel<<<1024 + 8192, 256>>>(tokens, embed, Wf, Wb);
    proj_corr_kernel<<<dim3(64, 16), 256, CORR_SMEM>>>(tokens, Wf, Wb, bf, bb);
    scan_kernel<<<128, 256, SCAN_SMEM>>>(lengths, Wf, Wb);
    transpose_kernel<<<1024 * 2 * 16, 256>>>(out);
}

// round 17
// speedup vs baseline: 1.4046x; 1.4046x over previous
#include <cuda_runtime.h>
#include <cuda_bf16.h>
#include <cuda_fp16.h>
#include <mma.h>
#include <cstdint>
#include <cstddef>

using namespace nvcuda;

// ---------------- device scratch (static, no runtime alloc) ----------------
__device__ float g_preF[(size_t)1024 * 64 * 2048];      // x@Wf[:512]+bf, time-major [t][b][g]
__device__ float g_preB[(size_t)1024 * 64 * 2048];      // x@Wb[:512]+bb
__device__ float g_base[2][256][2048];                  // embed@W[:512] per vocab entry
__device__ uint2 g_dropPack[(size_t)65536 * 128];       // per row: (d, bits(e[tok][d])) dropped entries
__device__ unsigned int g_dropN[65536];                 // per row: dropped count
__device__ uint2 g_kz[2 * 1024];                        // per-step zoneout keys (fwd, bwd)
__device__ uint2 g_kd;                                  // dropout key
// h exchange: 4 K-blocks per buffer. Block = [64 b rows][136 k] fp16 (row-major, ld=136).
// Block j = dims [128j, 128j+128), produced by CTAs 16j..16j+15.
#define LDAB 136
#define A_BLOCK_BYTES 17408u                            // 64*136*2
#define A_BLK_ELEMS (64 * LDAB)
__device__ __align__(1024) unsigned char g_hA[2][2][4][17408];
// per-CTA step flags, padded to 128B
struct FlagLine { unsigned v; unsigned pad[31]; };
__device__ FlagLine g_flag[2][64];
// time-major output scratch: [t][dir][d][b]
__device__ float g_outS[(size_t)1024 * 2 * 512 * 64];

// ---------------- JAX threefry2x32 (bit-exact, 20 rounds) ----------------
__device__ __forceinline__ uint32_t rotl32(uint32_t x, int r) { return (x << r) | (x >> (32 - r)); }

__device__ __forceinline__ void tf2x32(uint32_t k0, uint32_t k1, uint32_t& x0, uint32_t& x1) {
    uint32_t k2 = k0 ^ k1 ^ 0x1BD11BDAu;
    x0 += k0; x1 += k1;
#define TFR(r) { x0 += x1; x1 = rotl32(x1, r); x1 ^= x0; }
    TFR(13) TFR(15) TFR(26) TFR(6)   x0 += k1; x1 += k2 + 1u;
    TFR(17) TFR(29) TFR(16) TFR(24)  x0 += k2; x1 += k0 + 2u;
    TFR(13) TFR(15) TFR(26) TFR(6)   x0 += k0; x1 += k1 + 3u;
    TFR(17) TFR(29) TFR(16) TFR(24)  x0 += k1; x1 += k2 + 4u;
    TFR(13) TFR(15) TFR(26) TFR(6)   x0 += k2; x1 += k0 + 5u;
#undef TFR
}

__device__ __forceinline__ uint32_t pbits(uint32_t k0, uint32_t k1, uint32_t i) {
    uint32_t x0 = 0u, x1 = i;
    tf2x32(k0, k1, x0, x1);
    return x0 ^ x1;
}

__device__ __forceinline__ float u01(uint32_t bits) {
    return __uint_as_float((bits >> 9) | 0x3f800000u) - 1.0f;
}

// ---------------- MUFU-free transcendentals ----------------
__device__ __forceinline__ float sigm_fast(float x) {
    float t = -x * 1.44269504088896341f;
    t = fminf(fmaxf(t, -126.0f), 126.0f);
    float z = t + 12582912.0f;
    int ii = __float_as_int(z) - 0x4B400000;
    float f = t - (z - 12582912.0f);
    float p =            1.54035303933816e-4f;
    p = fmaf(p, f, 1.33335581464284e-3f);
    p = fmaf(p, f, 9.61812910762848e-3f);
    p = fmaf(p, f, 5.55041086648216e-2f);
    p = fmaf(p, f, 2.40226506959101e-1f);
    p = fmaf(p, f, 6.93147180559945e-1f);
    p = fmaf(p, f, 1.0f);
    float e = p * __int_as_float((ii + 127) << 23);
    float d = 1.0f + e;
    float y = __int_as_float(0x7EF311C3 - __float_as_int(d));
    y = y * (2.0f - d * y);
    y = y * (2.0f - d * y);
    y = y * (2.0f - d * y);
    return y;
}
__device__ __forceinline__ float tanh_fast(float x) {
    return fmaf(2.0f, sigm_fast(2.0f * x), -1.0f);
}

// ---------------- K1: setup — keys, flags, zero g_hA ----------------
__global__ void setup_kernel() {
    int tid = threadIdx.x;
    if (blockIdx.x == 0) {
        __shared__ uint32_t s[4];
        if (tid < 128) g_flag[tid >> 6][tid & 63].v = 0u;
        if (tid == 0) {
            uint32_t a, b;
            a = 0u; b = 0u; tf2x32(0u, 42u, a, b); g_kd = make_uint2(a, b);
            a = 0u; b = 1u; tf2x32(0u, 42u, a, b); s[0] = a; s[1] = b;   // kf
            a = 0u; b = 2u; tf2x32(0u, 42u, a, b); s[2] = a; s[3] = b;   // kb
        }
        __syncthreads();
        if (tid < 2) {
            uint32_t k0 = s[tid * 2], k1 = s[tid * 2 + 1];
            for (int t = 0; t < 1024; ++t) {
                uint32_t z0 = 0u, z1 = 0u; tf2x32(k0, k1, z0, z1);
                uint32_t n0 = 0u, n1 = 1u; tf2x32(k0, k1, n0, n1);
                g_kz[tid * 1024 + t] = make_uint2(z0, z1);
                k0 = n0; k1 = n1;
            }
        }
    }
    // zero g_hA: 2*2*4*17408 B = 69632 u32
    uint32_t* hA = (uint32_t*)&g_hA[0][0][0][0];
    for (unsigned i = blockIdx.x * 256u + tid; i < 69632u; i += gridDim.x * 256u)
        hA[i] = 0u;
}

// ---------------- K2: base table + dropout lists (fused) ----------------
__global__ void __launch_bounds__(256) basedrop_kernel(const int* __restrict__ tokens,
                                                       const float* __restrict__ embed,
                                                       const float* __restrict__ Wf,
                                                       const float* __restrict__ Wb) {
    int bid = blockIdx.x;
    int tid = threadIdx.x;
    if (bid < 1024) {
        int dir = bid >> 9;
        int rem = bid & 511;
        int gx = rem & 7, v0 = (rem >> 3) * 4;
        const float* W = dir ? Wb : Wf;
        int g = gx * 256 + tid;
        float acc0 = 0.f, acc1 = 0.f, acc2 = 0.f, acc3 = 0.f;
#pragma unroll 4
        for (int d = 0; d < 512; ++d) {
            float w = W[(size_t)d * 2048 + g];
            acc0 = fmaf(embed[(size_t)(v0 + 0) * 512 + d], w, acc0);
            acc1 = fmaf(embed[(size_t)(v0 + 1) * 512 + d], w, acc1);
            acc2 = fmaf(embed[(size_t)(v0 + 2) * 512 + d], w, acc2);
            acc3 = fmaf(embed[(size_t)(v0 + 3) * 512 + d], w, acc3);
        }
        g_base[dir][v0 + 0][g] = acc0;
        g_base[dir][v0 + 1][g] = acc1;
        g_base[dir][v0 + 2][g] = acc2;
        g_base[dir][v0 + 3][g] = acc3;
    } else {
        unsigned row = ((unsigned)(bid - 1024) * 256u + (unsigned)tid) >> 5;
        int lane = tid & 31;
        uint2 kd = g_kd;
        int tok = tokens[row];
        const float* erow = &embed[(size_t)tok * 512];
        uint2* outp = &g_dropPack[(size_t)row * 128];
        unsigned count = 0;
#pragma unroll 4
        for (int it = 0; it < 16; ++it) {
            int d = it * 32 + lane;
            uint32_t bits = pbits(kd.x, kd.y, row * 512u + (unsigned)d);
            bool dropped = !(u01(bits) < 0.9f);
            unsigned m = __ballot_sync(0xffffffffu, dropped);
            if (dropped) {
                unsigned pos = count + __popc(m & ((1u << lane) - 1u));
                outp[pos] = make_uint2((unsigned)d, __float_as_uint(erow[d]));
            }
            count += __popc(m);
        }
        if (lane == 0) g_dropN[row] = count;
    }
}

// ---------------- K3: projection (base + sparse dropout correction) ----------------
#define CORR_SMEM (512 * 64 * 4)

__global__ void __launch_bounds__(256, 1) proj_corr_kernel(const int* __restrict__ tokens,
                                                           const float* __restrict__ Wf,
                                                           const float* __restrict__ Wb,
                                                           const float* __restrict__ bf,
                                                           const float* __restrict__ bb) {
    extern __shared__ float sW[];
    int dir = blockIdx.x >> 5;
    int slice = blockIdx.x & 31;
    int g0 = slice * 64;
    const float* W = dir ? Wb : Wf;
    const float* bias = dir ? bb : bf;
    float* pre = dir ? g_preB : g_preF;
    const float* base = &g_base[dir][0][0];
    int tid = threadIdx.x;

    for (int i = tid; i < 512 * 64; i += 256)
        sW[i] = W[(size_t)(i >> 6) * 2048 + g0 + (i & 63)];
    __syncthreads();

    int lane = tid & 31, w = tid >> 5;
    float2 bv = *(const float2*)&bias[g0 + lane * 2];
    int rEnd = blockIdx.y * 4096 + 4096;
    for (int r = blockIdx.y * 4096 + w; r < rEnd; r += 8) {
        int tok = tokens[r];
        unsigned n = g_dropN[r];
        const uint2* lst = &g_dropPack[(size_t)r * 128];
        float2 acc = *(const float2*)&base[(size_t)tok * 2048 + g0 + lane * 2];
        for (unsigned j0 = 0; j0 < n; j0 += 32) {
            uint2 e = make_uint2(0u, 0u);
            if (j0 + lane < n) e = __ldcg(&lst[j0 + lane]);
#pragma unroll
            for (int jj = 0; jj < 32; ++jj) {
                unsigned dx = __shfl_sync(0xffffffffu, e.x, jj);
                unsigned dv = __shfl_sync(0xffffffffu, e.y, jj);
                float val = __uint_as_float(dv);
                float2 wv = *(const float2*)&sW[dx * 64 + lane * 2];
                acc.x = fmaf(-val, wv.x, acc.x);
                acc.y = fmaf(-val, wv.y, acc.y);
            }
        }
        int b = r >> 10, t = r & 1023;
        float2 o;
        o.x = fmaf(acc.x, (1.0f / 0.9f), bv.x);
        o.y = fmaf(acc.y, (1.0f / 0.9f), bv.y);
        *(float2*)&pre[(((size_t)t * 64) + b) * 2048 + g0 + lane * 2] = o;
    }
}

// ---------------- K4: persistent bidirectional LSTM scan ----------------
// fp16-h single tile (M=64) x fp16 hi/lo W pair, both products into one fp32 acc.
#define LDB 520
#define SA_OFF   0                                   // 4 blocks x 17408 = 69632
#define SBHI_OFF 69632
#define SBLO_OFF (SBHI_OFF + 32 * LDB * 2)           // 102912
#define SD_OFF   (SBLO_OFF + 32 * LDB * 2)           // 136192
#define LDD 40
#define SCAN_SMEM (SD_OFF + 64 * LDD * 4)            // 146432

__device__ __forceinline__ void wait_par(uint32_t bar, unsigned p) {
    asm volatile(
        "{\n\t.reg .pred P;\n\t"
        "WL_%=:\n\t"
        "mbarrier.try_wait.parity.acquire.cta.shared::cta.b64 P, [%0], %1, 0x989680;\n\t"
        "@P bra WD_%=;\n\t"
        "bra WL_%=;\n\t"
        "WD_%=:\n\t}"
        :: "r"(bar), "r"(p) : "memory");
}
__device__ __forceinline__ void tma_block(uint32_t dst, const unsigned char* src, uint32_t bar) {
    asm volatile("mbarrier.arrive.expect_tx.shared.b64 _, [%0], %1;"
                 :: "r"(bar), "r"(A_BLOCK_BYTES) : "memory");
    asm volatile("cp.async.bulk.shared::cta.global.mbarrier::complete_tx::bytes [%0], [%1], %2, [%3];"
                 :: "r"(dst), "l"(src), "r"(A_BLOCK_BYTES), "r"(bar) : "memory");
}

__global__ void __launch_bounds__(256, 1) scan_kernel(const int* __restrict__ lengths,
                                                      const float* __restrict__ Wf,
                                                      const float* __restrict__ Wb) {
    extern __shared__ unsigned char smem[];
    half* sA   = (half*)(smem + SA_OFF);             // 4 blocks, each [64 b][136 k] fp16
    half* sBhi = (half*)(smem + SBHI_OFF);           // [32 n][520 k]
    half* sBlo = (half*)(smem + SBLO_OFF);
    float* sD  = (float*)(smem + SD_OFF);            // [64 b][40]
    __shared__ int sLen[64];
    __shared__ __align__(8) unsigned long long mbars[4];

    int dir = blockIdx.x >> 6, cta = blockIdx.x & 63, d0 = cta * 8;
    int tid = threadIdx.x, wid = tid >> 5, lane = tid & 31;
    const float* W = dir ? Wb : Wf;

    uint32_t sA_addr = (uint32_t)__cvta_generic_to_shared(sA);
    uint32_t bar[4];
#pragma unroll
    for (int j = 0; j < 4; ++j) bar[j] = (uint32_t)__cvta_generic_to_shared(&mbars[j]);
    if (tid < 4)
        asm volatile("mbarrier.init.shared.b64 [%0], 1;" :: "r"(bar[tid]) : "memory");

    // W slice -> fp16 hi/lo, [n][k] with k contiguous (col_major fragment view)
    for (int i = tid; i < 32 * 512; i += 256) {
        int n = i & 31, k = i >> 5;
        float w = W[(size_t)(512 + k) * 2048 + ((n >> 3) << 9) + d0 + (n & 7)];
        half hi = __float2half(w);
        half lo = __float2half(w - __half2float(hi));
        sBhi[n * LDB + k] = hi;
        sBlo[n * LDB + k] = lo;
    }
    if (tid < 64) sLen[tid] = lengths[tid];
    __syncthreads();

    if (tid < 4) tma_block(sA_addr + (unsigned)tid * A_BLOCK_BYTES, g_hA[dir][0][tid], bar[tid]);

    int q = tid >> 6, b = tid & 63;
    int dd = q * 2, d = d0 + dd;
    float c0r = 0.f, c1r = 0.f;
    float hp0r = 0.f, hp1r = 0.f;
    const float* pre = dir ? g_preB : g_preF;
    int mg = wid & 3, nt = wid >> 2;                 // warp tile: m-tile mg (16 b), n-tile nt (16 g)
    int blk = cta >> 4;
    unsigned colw = (unsigned)(d & 127);             // k-col within block
    size_t offA = (size_t)(b * LDAB + colw) * 2;     // byte offset of (b, d) fp16 pair
    unsigned p0 = (unsigned)(b * 512 + d);

    for (int s = 0; s < 1024; ++s) {
        int tx = dir ? (1023 - s) : s;
        unsigned par = (unsigned)(s & 1);

        size_t prow = ((size_t)tx * 64 + b) * 2048 + (size_t)d;
        float2 pxi = *(const float2*)&pre[prow];
        float2 pxg = *(const float2*)&pre[prow + 512];
        float2 pxf = *(const float2*)&pre[prow + 1024];
        float2 pxo = *(const float2*)&pre[prow + 1536];
        uint2 kz = __ldg(&g_kz[dir * 1024 + s]);
        bool kh0 = u01(pbits(kz.x, kz.y, p0)) < 0.1f;
        bool kh1 = u01(pbits(kz.x, kz.y, p0 + 1u)) < 0.1f;
        bool kc0 = u01(pbits(kz.x, kz.y, p0 + 32768u)) < 0.1f;
        bool kc1 = u01(pbits(kz.x, kz.y, p0 + 32769u)) < 0.1f;

        // ---- WMMA: one 16x16 tile per warp; W_hi and W_lo into the same accumulator ----
        wmma::fragment<wmma::accumulator, 16, 16, 16, float> acc;
        wmma::fill_fragment(acc, 0.0f);
        const half* bh_base = sBhi + nt * 16 * LDB;
        const half* bl_base = sBlo + nt * 16 * LDB;

#pragma unroll 1
        for (int bk = 0; bk < 4; ++bk) {
            wait_par(bar[bk], par);
            const half* ap = sA + bk * A_BLK_ELEMS + (mg * 16) * LDAB;
            const half* bhp = bh_base + bk * 128;
            const half* blp = bl_base + bk * 128;
#pragma unroll 4
            for (int kt = 0; kt < 8; ++kt) {
                wmma::fragment<wmma::matrix_a, 16, 16, 16, half, wmma::row_major> af;
                wmma::fragment<wmma::matrix_b, 16, 16, 16, half, wmma::col_major> bhf, blf;
                wmma::load_matrix_sync(af, ap + kt * 16, LDAB);
                wmma::load_matrix_sync(bhf, bhp + kt * 16, LDB);
                wmma::load_matrix_sync(blf, blp + kt * 16, LDB);
                wmma::mma_sync(acc, af, bhf, acc);
                wmma::mma_sync(acc, af, blf, acc);
            }
        }
        wmma::store_matrix_sync(sD + (mg * 16) * LDD + nt * 16, acc, LDD, wmma::mem_row_major);
        __syncthreads();

        // ---- gates + zoneout ----
        if (dir && (1023 - s) < sLen[b] - 1) { c0r = 0.f; c1r = 0.f; }
        const float* dt = &sD[b * LDD];
        float a_i0 = dt[dd],      a_i1 = dt[dd + 1];
        float a_g0 = dt[8 + dd],  a_g1 = dt[9 + dd];
        float a_f0 = dt[16 + dd], a_f1 = dt[17 + dd];
        float a_o0 = dt[24 + dd], a_o1 = dt[25 + dd];
        float f0 = sigm_fast(pxf.x + a_f0 + 1.f), f1 = sigm_fast(pxf.y + a_f1 + 1.f);
        float o0 = sigm_fast(pxo.x + a_o0), o1 = sigm_fast(pxo.y + a_o1);
        float cn0 = f0 * c0r + sigm_fast(pxi.x + a_i0) * tanh_fast(pxg.x + a_g0);
        float cn1 = f1 * c1r + sigm_fast(pxi.y + a_i1) * tanh_fast(pxg.y + a_g1);
        float hn0 = o0 * tanh_fast(cn0);
        float hn1 = o1 * tanh_fast(cn1);
        float ho0 = kh0 ? hp0r : hn0;
        float ho1 = kh1 ? hp1r : hn1;
        c0r = kc0 ? c0r : cn0;
        c1r = kc1 ? c1r : cn1;

        // ---- next-step h (bwd reset pre-applied) as one fp16 pair ----
        float w0 = ho0, w1 = ho1;
        if (dir && (1022 - s) < sLen[b] - 1) { w0 = 0.f; w1 = 0.f; }
        hp0r = w0; hp1r = w1;
        half h0 = __float2half(w0), h1 = __float2half(w1);
        unsigned char* hw = g_hA[dir][(s + 1) & 1][blk];
        uint32_t hv = (uint32_t)__half_as_ushort(h0) | ((uint32_t)__half_as_ushort(h1) << 16);
        __stcg((uint32_t*)(hw + offA), hv);

        float* os = &g_outS[(((size_t)tx * 2 + dir) * 512 + d) * 64 + b];

        __syncthreads();
        if (s < 1023) {
            if (tid == 0) {
                __threadfence();
                *(volatile unsigned*)&g_flag[dir][cta].v = (unsigned)(s + 1);
            }
            os[0] = ho0;
            os[64] = ho1;
            if (wid < 4) {
                if (lane < 16) {
                    volatile unsigned* f = &g_flag[dir][wid * 16 + lane].v;
                    while (*f < (unsigned)(s + 1)) __nanosleep(64);
                }
                __syncwarp();
                if (lane == 0)
                    tma_block(sA_addr + (unsigned)wid * A_BLOCK_BYTES,
                              g_hA[dir][(s + 1) & 1][wid], bar[wid]);
            }
        } else {
            os[0] = ho0;
            os[64] = ho1;
        }
    }
}

// ---------------- K5: transpose g_outS -> out [b][l][2*512] ----------------
__global__ void __launch_bounds__(256) transpose_kernel(float* __restrict__ out) {
    __shared__ float sT[32][65];
    unsigned bid = blockIdx.x;
    int dblk = bid & 15;
    int dir = (bid >> 4) & 1;
    int l = bid >> 5;
    const float* src = &g_outS[(((size_t)l * 2 + dir) * 512 + dblk * 32) * 64];
    int tid = threadIdx.x;
#pragma unroll
    for (int i = 0; i < 8; ++i) {
        int idx = tid + i * 256;
        int r = idx >> 6, c = idx & 63;
        sT[r][c] = src[idx];
    }
    __syncthreads();
#pragma unroll
    for (int i = 0; i < 8; ++i) {
        int idx = tid + i * 256;
        int b = idx >> 5, r = idx & 31;
        out[((size_t)b * 1024 + l) * 1024 + dir * 512 + dblk * 32 + r] = sT[r][b];
    }
}

// ---------------- launch ----------------
extern "C" void kernel_launch(void* const* d_in, const int* in_sizes, int n_in,
                              void* d_out, int out_size) {
    (void)in_sizes; (void)n_in; (void)out_size;
    const int*   tokens  = (const int*)d_in[0];
    const int*   lengths = (const int*)d_in[1];
    const float* embed   = (const float*)d_in[2];
    const float* Wf      = (const float*)d_in[3];
    const float* bf      = (const float*)d_in[4];
    const float* Wb      = (const float*)d_in[5];
    const float* bb      = (const float*)d_in[6];
    float* out = (float*)d_out;

    cudaFuncSetAttribute(scan_kernel, cudaFuncAttributeMaxDynamicSharedMemorySize, SCAN_SMEM);
    cudaFuncSetAttribute(proj_corr_kernel, cudaFuncAttributeMaxDynamicSharedMemorySize, CORR_SMEM);

    setup_kernel<<<64, 256>>>();
    basedrop_kernel<<<1024 + 8192, 256>>>(tokens, embed, Wf, Wb);
    proj_corr_kernel<<<dim3(64, 16), 256, CORR_SMEM>>>(tokens, Wf, Wb, bf, bb);
    scan_kernel<<<128, 256, SCAN_SMEM>>>(lengths, Wf, Wb);
    transpose_kernel<<<1024 * 2 * 16, 256>>>(out);
}